// round 8
// baseline (speedup 1.0000x reference)
#include <cuda_runtime.h>
#include <cuda_bf16.h>
#include <math.h>
#include <stdint.h>

#define T_  256
#define B_  64
#define H_  768
#define NH_ 12
#define HD_ 64
#define G4H 3072
#define QKVW 2304
#define NTHREADS 512
#define SK_G 6
#define SK_Q 4
#define SK_F 12

#define TSK_G (16*16*64)
#define TSK_Q (12*8*64)
#define TSK_F (8*8*64)
#define SOFF_WQ 131072
#define SOFF_WF 180224
#define SOFF_A  212992
#define SOFF_RP 229376
#define SMEM_TOTAL 230400

__device__ __align__(256) float g_newvAll[T_*B_*H_];
__device__ __align__(256) float g_qkvp[SK_Q*2*B_*QKVW];
__device__ __align__(256) float g_ctx[B_*2*H_];
__device__ __align__(256) float g_fp[SK_F*B_*H_];
__device__ __align__(256) float g_gp[SK_G*B_*G4H];
__device__ __align__(256) float g_base[B_*G4H];
__device__ __align__(256) float g_h[B_*H_];
__device__ __align__(256) float g_c[B_*H_];
__device__ unsigned g_cnt = 0;
__device__ unsigned g_gen = 0;

__device__ __align__(256) uint2 WbaseF[144*TSK_G];
__device__ __align__(256) uint2 WgF[144*TSK_G];
__device__ __align__(256) uint2 WqF[144*TSK_Q];
__device__ __align__(256) uint2 WfF[144*TSK_F];

__device__ __forceinline__ void gsync() {
    __syncthreads();
    if (threadIdx.x == 0) {
        __threadfence();
        unsigned g = *(volatile unsigned*)&g_gen;
        unsigned a = atomicAdd(&g_cnt, 1u);
        if (a == gridDim.x - 1u) {
            *(volatile unsigned*)&g_cnt = 0u;
            __threadfence();
            *(volatile unsigned*)&g_gen = g + 1u;
        } else {
            while (*(volatile unsigned*)&g_gen == g) { }
        }
        __threadfence();
    }
    __syncthreads();
}
__device__ __forceinline__ float wsum(float v) {
    #pragma unroll
    for (int o = 16; o > 0; o >>= 1) v += __shfl_xor_sync(0xffffffffu, v, o);
    return v;
}
__device__ __forceinline__ float sigm(float v) { return 1.f / (1.f + expf(-v)); }
__device__ __forceinline__ uint32_t pkhi(float a, float b) {
    __nv_bfloat162 t = __floats2bfloat162_rn(a, b);
    return *(uint32_t*)&t;
}
__device__ __forceinline__ uint32_t pklo(float a, float b) {
    float ra = a - __bfloat162float(__float2bfloat16(a));
    float rb = b - __bfloat162float(__float2bfloat16(b));
    return pkhi(ra, rb);
}
__device__ __forceinline__ void split2(float2 v, uint32_t& h, uint32_t& l) {
    h = pkhi(v.x, v.y);
    l = pklo(v.x, v.y);
}
__device__ __forceinline__ void mma16816(float* c, const uint32_t* a, const uint32_t* b) {
    asm volatile(
        "mma.sync.aligned.m16n8k16.row.col.f32.bf16.bf16.f32 "
        "{%0,%1,%2,%3}, {%4,%5,%6,%7}, {%8,%9}, {%0,%1,%2,%3};"
        : "+f"(c[0]), "+f"(c[1]), "+f"(c[2]), "+f"(c[3])
        : "r"(a[0]), "r"(a[1]), "r"(a[2]), "r"(a[3]), "r"(b[0]), "r"(b[1]));
}

__device__ __forceinline__ void stA_slot(uint4* sA, int slotBase, int lane,
                                         const float* p1, const float* p2, int c1) {
    float2 v00 = *(const float2*)(p1 + c1);
    float2 v01 = *(const float2*)(p1 + c1 + 8);
    float2 v10 = *(const float2*)(p2 + c1);
    float2 v11 = *(const float2*)(p2 + c1 + 8);
    uint4 Hv, Lv;
    split2(v00, Hv.x, Lv.x);
    split2(v10, Hv.y, Lv.y);
    split2(v01, Hv.z, Lv.z);
    split2(v11, Hv.w, Lv.w);
    sA[slotBase + lane]      = Hv;
    sA[slotBase + 32 + lane] = Lv;
}
// 64-row A, 32-k stage (first 256 threads)
__device__ __forceinline__ void stageA_g(uint4* sA, int buf, const float* Ab, int lda, int c0) {
    const int tid = threadIdx.x;
    if (tid >= 256) return;
    const int kt = tid >> 7, mt = (tid >> 5) & 3, lane = tid & 31;
    const int rr = lane >> 2, kp = lane & 3;
    const float* p1 = Ab + (size_t)(mt * 16 + rr) * lda;
    stA_slot(sA, ((buf * 2 + kt) * 4 + mt) * 64, lane, p1, p1 + 8 * lda, c0 + kt * 16 + kp * 2);
}
// 128-row A via row pointers, 16-k stage (first 256 threads)
__device__ __forceinline__ void stageA_q(uint4* sA, int buf, const float* const* rowp, int c0) {
    const int tid = threadIdx.x;
    if (tid >= 256) return;
    const int mt = tid >> 5, lane = tid & 31;
    const int rr = lane >> 2, kp = lane & 3;
    stA_slot(sA, (buf * 8 + mt) * 64, lane, rowp[mt * 16 + rr], rowp[mt * 16 + rr + 8],
             c0 + kp * 2);
}

// 16 warps: MI=1 (one m16 tile per warp). warp grid: (16/NWARP) m x NWARP n
template<int KTPS, int MTOT, int NWARP, int NJ, int NGTOT>
__device__ __forceinline__ void comp_stage(const uint4* sA, const uint2* sW,
                                           int buf, int s, float acc[NJ][4]) {
    const int w = threadIdx.x >> 5, lane = threadIdx.x & 31;
    const int mw = w / NWARP, nw = w % NWARP;
    #pragma unroll
    for (int kt = 0; kt < KTPS; kt++) {
        const int ktg = s * KTPS + kt;
        const int sl = ((buf * KTPS + kt) * MTOT + mw) * 64;
        uint4 ah = sA[sl + lane];
        uint4 al = sA[sl + 32 + lane];
        #pragma unroll
        for (int j = 0; j < NJ; j++) {
            const uint2* wb = sW + (size_t)(ktg * NGTOT + nw * NJ + j) * 64;
            uint2 bh = wb[lane];
            uint2 bl = wb[32 + lane];
            mma16816(acc[j], (const uint32_t*)&ah, (const uint32_t*)&bh);
            mma16816(acc[j], (const uint32_t*)&ah, (const uint32_t*)&bl);
            mma16816(acc[j], (const uint32_t*)&al, (const uint32_t*)&bh);
        }
    }
}
template<int NWARP, int NJ>
__device__ __forceinline__ void epi(const float acc[NJ][4], float* C, int ldc) {
    const int w = threadIdx.x >> 5, lane = threadIdx.x & 31;
    const int mw = w / NWARP, nw = w % NWARP;
    const int g = lane >> 2, tg = lane & 3;
    #pragma unroll
    for (int j = 0; j < NJ; j++) {
        float* d0 = C + (size_t)(mw * 16 + g) * ldc + (nw * NJ + j) * 8 + 2 * tg;
        *(float2*)d0             = make_float2(acc[j][0], acc[j][1]);
        *(float2*)(d0 + 8 * ldc) = make_float2(acc[j][2], acc[j][3]);
    }
}

__global__ void prep_kernel(const float* __restrict__ Wqh, const float* __restrict__ Wah,
                            const float* __restrict__ Wih, const float* __restrict__ Whh,
                            const float* __restrict__ Wq,  const float* __restrict__ Wk,
                            const float* __restrict__ Wv,  const float* __restrict__ Wfuse)
{
    const int idx0 = blockIdx.x * blockDim.x + threadIdx.x;
    const int stride = gridDim.x * blockDim.x;
    const int EG = 144 * 16 * 16 * 32;
    for (int e = idx0; e < EG; e += stride) {
        int lane = e & 31; int r = e >> 5;
        int ng = r & 15; r >>= 4;
        int kt = r & 15; r >>= 4;
        int task = r;
        int nt = task / 6, kc = task % 6;
        int n = nt * 128 + ng * 8 + (lane >> 2);
        int k = kc * 256 + kt * 16 + ((lane & 3) << 1);
        size_t o = (size_t)task * TSK_G + (kt * 16 + ng) * 64 + lane;
        {
            float v0, v1, v2, v3;
            if (k < H_) { v0 = Wqh[(size_t)k*G4H+n]; v1 = Wqh[(size_t)(k+1)*G4H+n];
                          v2 = Wqh[(size_t)(k+8)*G4H+n]; v3 = Wqh[(size_t)(k+9)*G4H+n]; }
            else { int kk = k - H_; v0 = Wah[(size_t)kk*G4H+n]; v1 = Wah[(size_t)(kk+1)*G4H+n];
                   v2 = Wah[(size_t)(kk+8)*G4H+n]; v3 = Wah[(size_t)(kk+9)*G4H+n]; }
            WbaseF[o]      = make_uint2(pkhi(v0, v1), pkhi(v2, v3));
            WbaseF[o + 32] = make_uint2(pklo(v0, v1), pklo(v2, v3));
        }
        {
            float v0, v1, v2, v3;
            if (k < H_) { v0 = Wih[(size_t)k*G4H+n]; v1 = Wih[(size_t)(k+1)*G4H+n];
                          v2 = Wih[(size_t)(k+8)*G4H+n]; v3 = Wih[(size_t)(k+9)*G4H+n]; }
            else { int kk = k - H_; v0 = Whh[(size_t)kk*G4H+n]; v1 = Whh[(size_t)(kk+1)*G4H+n];
                   v2 = Whh[(size_t)(kk+8)*G4H+n]; v3 = Whh[(size_t)(kk+9)*G4H+n]; }
            WgF[o]      = make_uint2(pkhi(v0, v1), pkhi(v2, v3));
            WgF[o + 32] = make_uint2(pklo(v0, v1), pklo(v2, v3));
        }
    }
    const int EQ = 144 * 12 * 8 * 32;
    for (int e = idx0; e < EQ; e += stride) {
        int lane = e & 31; int r = e >> 5;
        int ng = r & 7; r >>= 3;
        int kt = r % 12; int task = r / 12;
        int nt = task / 4, kc = task % 4;
        int n = nt * 64 + ng * 8 + (lane >> 2);
        int k = kc * 192 + kt * 16 + ((lane & 3) << 1);
        int ws = n / H_, nc = n - ws * H_;
        const float* W = (ws == 0) ? Wq : ((ws == 1) ? Wk : Wv);
        float v0 = W[(size_t)k*H_+nc],     v1 = W[(size_t)(k+1)*H_+nc];
        float v2 = W[(size_t)(k+8)*H_+nc], v3 = W[(size_t)(k+9)*H_+nc];
        size_t o = (size_t)task * TSK_Q + (kt * 8 + ng) * 64 + lane;
        WqF[o]      = make_uint2(pkhi(v0, v1), pkhi(v2, v3));
        WqF[o + 32] = make_uint2(pklo(v0, v1), pklo(v2, v3));
    }
    const int EF = 144 * 8 * 8 * 32;
    for (int e = idx0; e < EF; e += stride) {
        int lane = e & 31; int r = e >> 5;
        int ng = r & 7; r >>= 3;
        int kt = r & 7; r >>= 3;
        int task = r;
        int nt = task / 12, kc = task % 12;
        int n = nt * 64 + ng * 8 + (lane >> 2);
        int k = kc * 128 + kt * 16 + ((lane & 3) << 1);
        float v0 = Wfuse[(size_t)k*H_+n],     v1 = Wfuse[(size_t)(k+1)*H_+n];
        float v2 = Wfuse[(size_t)(k+8)*H_+n], v3 = Wfuse[(size_t)(k+9)*H_+n];
        size_t o = (size_t)task * TSK_F + (kt * 8 + ng) * 64 + lane;
        WfF[o]      = make_uint2(pkhi(v0, v1), pkhi(v2, v3));
        WfF[o + 32] = make_uint2(pklo(v0, v1), pklo(v2, v3));
    }
}

__global__ void __launch_bounds__(NTHREADS, 1)
sqac_kernel(const float* __restrict__ question, const float* __restrict__ answer,
            const float* __restrict__ x, const int* __restrict__ ping,
            const float* __restrict__ h0, const float* __restrict__ c0,
            const float* __restrict__ bqh, const float* __restrict__ bah,
            const float* __restrict__ bih, const float* __restrict__ bhh,
            const float* __restrict__ bq,  const float* __restrict__ bk,
            const float* __restrict__ bv,  const float* __restrict__ bfuse,
            float* __restrict__ out)
{
    extern __shared__ __align__(16) char smem[];
    uint2* sWg = (uint2*)smem;
    uint2* sWq = (uint2*)(smem + SOFF_WQ);
    uint2* sWf = (uint2*)(smem + SOFF_WF);
    uint4* sA  = (uint4*)(smem + SOFF_A);
    const float** rowp = (const float**)(smem + SOFF_RP);

    const int idx0   = blockIdx.x * blockDim.x + threadIdx.x;
    const int stride = gridDim.x * blockDim.x;
    const int bid    = blockIdx.x;
    const int nblk   = gridDim.x;
    const int tid    = threadIdx.x;

    // ---- prologue: pin weights, init state, base GEMM --------------------
    if (bid < 144) {
        const uint4* s1 = (const uint4*)(WbaseF + (size_t)bid * TSK_G);
        for (int i = tid; i < TSK_G / 2; i += NTHREADS) ((uint4*)sWg)[i] = s1[i];
        const uint4* s2 = (const uint4*)(WqF + (size_t)bid * TSK_Q);
        for (int i = tid; i < TSK_Q / 2; i += NTHREADS) ((uint4*)sWq)[i] = s2[i];
        const uint4* s3 = (const uint4*)(WfF + (size_t)bid * TSK_F);
        for (int i = tid; i < TSK_F / 2; i += NTHREADS) ((uint4*)sWf)[i] = s3[i];
    }
    for (int idx = idx0; idx < B_ * H_; idx += stride) {
        g_h[idx] = h0[idx];
        g_c[idx] = c0[idx];
        g_newvAll[idx] = x[idx];
    }
    __syncthreads();

    if (bid < 144) {
        const int nt = bid / 6, kc = bid % 6;
        const float* Ab = (kc < 3) ? (question + kc * 256) : (answer + (kc - 3) * 256);
        float acc[4][4] = {};
        stageA_g(sA, 0, Ab, H_, 0);
        __syncthreads();
        for (int s = 0; s < 8; s++) {
            if (s < 7) stageA_g(sA, (s + 1) & 1, Ab, H_, (s + 1) * 32);
            comp_stage<2, 4, 4, 4, 16>(sA, sWg, s & 1, s, acc);
            __syncthreads();
        }
        epi<4, 4>(acc, g_gp + (size_t)kc * (B_ * G4H) + nt * 128, G4H);
        __syncthreads();
        const uint4* s1 = (const uint4*)(WgF + (size_t)bid * TSK_G);
        for (int i = tid; i < TSK_G / 2; i += NTHREADS) ((uint4*)sWg)[i] = s1[i];
    }
    gsync();

    for (int idx = idx0; idx < B_ * G4H; idx += stride) {
        int n = idx % G4H;
        float s = bqh[n] + bah[n] + bih[n] + bhh[n];
        #pragma unroll
        for (int kc = 0; kc < SK_G; kc++) s += g_gp[(size_t)kc * (B_ * G4H) + idx];
        g_base[idx] = s;
    }
    gsync();

    // =======================================================================
    for (int t = 0; t < T_; t++) {
        // ---- X: gates(t) + QKV(t+1) on pinned weights ---------------------
        if (bid < 144) {
            {
                const int nt = bid / 6, kc = bid % 6;
                const float* Ab = (kc < 3) ? (g_newvAll + (size_t)t * (B_ * H_) + kc * 256)
                                           : (g_h + (kc - 3) * 256);
                float acc[4][4] = {};
                stageA_g(sA, 0, Ab, H_, 0);
                __syncthreads();
                for (int s = 0; s < 8; s++) {
                    if (s < 7) stageA_g(sA, (s + 1) & 1, Ab, H_, (s + 1) * 32);
                    comp_stage<2, 4, 4, 4, 16>(sA, sWg, s & 1, s, acc);
                    __syncthreads();
                }
                epi<4, 4>(acc, g_gp + (size_t)kc * (B_ * G4H) + nt * 128, G4H);
                __syncthreads();
            }
            if (t + 1 < T_) {
                if (tid < 128) {
                    int m = tid, b = m >> 1, s2 = m & 1;
                    const float* p;
                    if (s2) {
                        p = x + ((size_t)(t + 1) * B_ + b) * H_;
                    } else {
                        int pt = ping[b * T_ + (t + 1)];
                        int i2 = pt - 1;
                        i2 = i2 < 0 ? 0 : (i2 > T_ - 1 ? T_ - 1 : i2);
                        p = ((i2 <= t) ? g_newvAll : x) + ((size_t)i2 * B_ + b) * H_;
                    }
                    rowp[m] = p;
                }
                __syncthreads();
                const int nt = bid / 4, kc = bid % 4;
                const int c0 = kc * 192;
                float acc[4][4] = {};
                stageA_q(sA, 0, rowp, c0);
                __syncthreads();
                for (int s = 0; s < 12; s++) {
                    if (s < 11) stageA_q(sA, (s + 1) & 1, rowp, c0 + (s + 1) * 16);
                    comp_stage<1, 8, 2, 4, 8>(sA, sWq, s & 1, s, acc);
                    __syncthreads();
                }
                epi<2, 4>(acc, g_qkvp + (size_t)kc * (2 * B_ * QKVW) + nt * 64, QKVW);
            }
        }
        gsync();

        // ---- Y: attention(t+1) + LSTM pointwise(t) -------------------------
        if (t + 1 < T_) {
            int wid = bid * (NTHREADS / 32) + (tid >> 5);
            int lane = tid & 31;
            for (int task = wid; task < B_ * NH_; task += nblk * (NTHREADS / 32)) {
                int b = task / NH_, h = task - b * NH_;
                float q[2][2], kk2[2][2], vv[2][2];
                #pragma unroll
                for (int s = 0; s < 2; s++) {
                    int row = (b * 2 + s) * QKVW;
                    #pragma unroll
                    for (int dd = 0; dd < 2; dd++) {
                        int col = h * HD_ + lane + dd * 32;
                        float qv = bq[col], kv = bk[col], vvv = bv[col];
                        #pragma unroll
                        for (int kc = 0; kc < SK_Q; kc++) {
                            const float* p = g_qkvp + (size_t)kc * (2 * B_ * QKVW) + row;
                            qv  += p[col];
                            kv  += p[H_ + col];
                            vvv += p[2 * H_ + col];
                        }
                        q[s][dd] = qv; kk2[s][dd] = kv; vv[s][dd] = vvv;
                    }
                }
                float s00 = wsum(q[0][0]*kk2[0][0] + q[0][1]*kk2[0][1]) * 0.125f;
                float s01 = wsum(q[0][0]*kk2[1][0] + q[0][1]*kk2[1][1]) * 0.125f;
                float s10 = wsum(q[1][0]*kk2[0][0] + q[1][1]*kk2[0][1]) * 0.125f;
                float s11 = wsum(q[1][0]*kk2[1][0] + q[1][1]*kk2[1][1]) * 0.125f;
                float m0 = fmaxf(s00, s01), m1 = fmaxf(s10, s11);
                float e00 = expf(s00 - m0), e01 = expf(s01 - m0);
                float e10 = expf(s10 - m1), e11 = expf(s11 - m1);
                float r0 = 1.f / (e00 + e01), r1 = 1.f / (e10 + e11);
                float p00 = e00 * r0, p01 = e01 * r0, p10 = e10 * r1, p11 = e11 * r1;
                #pragma unroll
                for (int dd = 0; dd < 2; dd++) {
                    int d = lane + dd * 32;
                    g_ctx[b * (2*H_) + h * HD_ + d]      = p00 * vv[0][dd] + p01 * vv[1][dd];
                    g_ctx[b * (2*H_) + H_ + h * HD_ + d] = p10 * vv[0][dd] + p11 * vv[1][dd];
                }
            }
        }
        for (int idx = idx0; idx < B_ * H_; idx += stride) {
            int b = idx / H_, j = idx - b * H_;
            float gg[4];
            #pragma unroll
            for (int u = 0; u < 4; u++) {
                int col = b * G4H + u * H_ + j;
                float s = g_base[col];
                #pragma unroll
                for (int kc = 0; kc < SK_G; kc++) s += g_gp[(size_t)kc * (B_ * G4H) + col];
                gg[u] = s;
            }
            float iv = sigm(gg[0]);
            float fv = sigm(gg[1]);
            float gv = tanhf(gg[2]);
            float ov = sigm(gg[3]);
            float c = fv * g_c[idx] + iv * gv;
            float h = ov * tanhf(c);
            g_c[idx] = c;
            g_h[idx] = h;
            out[((size_t)t * B_ + b) * H_ + j] = h;
            if (t == T_ - 1) {
                out[((size_t)T_ * B_ + b) * H_ + j]       = h;
                out[((size_t)(T_ + 1) * B_ + b) * H_ + j] = c;
            }
        }
        gsync();

        if (t + 1 < T_) {
            // ---- Z: fuse(t+1) on pinned weights ------------------------------
            if (bid < 144) {
                const int nt = bid / 12, kc = bid % 12;
                const float* Ab = g_ctx + kc * 128;
                float acc[2][4] = {};
                stageA_g(sA, 0, Ab, 2 * H_, 0);
                __syncthreads();
                for (int s = 0; s < 4; s++) {
                    if (s < 3) stageA_g(sA, (s + 1) & 1, Ab, 2 * H_, (s + 1) * 32);
                    comp_stage<2, 4, 4, 2, 8>(sA, sWf, s & 1, s, acc);
                    __syncthreads();
                }
                epi<4, 2>(acc, g_fp + (size_t)kc * (B_ * H_) + nt * 64, H_);
            }
            gsync();

            // ---- W: combine fuse + select -> newv(t+1) ------------------------
            for (int idx = idx0; idx < B_ * H_; idx += stride) {
                int b = idx / H_, j = idx - b * H_;
                float e = bfuse[j];
                #pragma unroll
                for (int kc = 0; kc < SK_F; kc++) e += g_fp[(size_t)kc * (B_ * H_) + idx];
                int pt = ping[b * T_ + (t + 1)];
                float right = x[((size_t)(t + 1) * B_ + b) * H_ + j];
                g_newvAll[(size_t)(t + 1) * (B_ * H_) + idx] = (pt > 0) ? e : right;
            }
            gsync();
        }
    }
}

extern "C" void kernel_launch(void* const* d_in, const int* in_sizes, int n_in,
                              void* d_out, int out_size)
{
    (void)in_sizes; (void)n_in; (void)out_size;
    const float* question = (const float*)d_in[0];
    const float* answer   = (const float*)d_in[1];
    const float* x        = (const float*)d_in[2];
    const int*   ping     = (const int*)  d_in[3];
    const float* h0       = (const float*)d_in[4];
    const float* c0       = (const float*)d_in[5];
    const float* Wqh      = (const float*)d_in[6];
    const float* bqh      = (const float*)d_in[7];
    const float* Wah      = (const float*)d_in[8];
    const float* bah      = (const float*)d_in[9];
    const float* Wih      = (const float*)d_in[10];
    const float* bih      = (const float*)d_in[11];
    const float* Whh      = (const float*)d_in[12];
    const float* bhh      = (const float*)d_in[13];
    const float* Wq       = (const float*)d_in[14];
    const float* bq       = (const float*)d_in[15];
    const float* Wk       = (const float*)d_in[16];
    const float* bk       = (const float*)d_in[17];
    const float* Wv       = (const float*)d_in[18];
    const float* bv       = (const float*)d_in[19];
    const float* Wfuse    = (const float*)d_in[20];
    const float* bfuse    = (const float*)d_in[21];

    int dev = 0;
    cudaGetDevice(&dev);
    int nsm = 148;
    cudaDeviceGetAttribute(&nsm, cudaDevAttrMultiProcessorCount, dev);

    cudaFuncSetAttribute(sqac_kernel, cudaFuncAttributeMaxDynamicSharedMemorySize, SMEM_TOTAL);

    prep_kernel<<<nsm * 8, 256>>>(Wqh, Wah, Wih, Whh, Wq, Wk, Wv, Wfuse);
    sqac_kernel<<<nsm, NTHREADS, SMEM_TOTAL>>>(question, answer, x, ping, h0, c0,
                                               bqh, bah, bih, bhh, bq, bk, bv, bfuse,
                                               (float*)d_out);
}

// round 9
// speedup vs baseline: 1.0788x; 1.0788x over previous
#include <cuda_runtime.h>
#include <cuda_fp16.h>
#include <math.h>
#include <stdint.h>

#define T_  256
#define B_  64
#define H_  768
#define NH_ 12
#define HD_ 64
#define G4H 3072
#define QKVW 2304
#define NTHREADS 512
#define SK_G 6
#define SK_Q 4
#define SK_F 12

// fragment strides (uint2 units) per task — single-fp16 B
#define TSK_G (16*16*32)
#define TSK_Q (12*8*32)
#define TSK_F (8*8*32)
#define SOFF_WQ 65536
#define SOFF_WF 90112
#define SOFF_A  106496
#define SOFF_RP 122880
#define SMEM_TOTAL 123904

__device__ __align__(256) float g_newvAll[T_*B_*H_];
__device__ __align__(256) float g_qkvp[SK_Q*2*B_*QKVW];
__device__ __align__(256) float g_ctx[B_*2*H_];
__device__ __align__(256) float g_fp[SK_F*B_*H_];
__device__ __align__(256) float g_gp[SK_G*B_*G4H];
__device__ __align__(256) float g_base[B_*G4H];
__device__ __align__(256) float g_h[B_*H_];
__device__ __align__(256) float g_c[B_*H_];
__device__ unsigned g_cnt = 0;
__device__ unsigned g_gen = 0;

__device__ __align__(256) uint2 WbaseF[144*TSK_G];
__device__ __align__(256) uint2 WgF[144*TSK_G];
__device__ __align__(256) uint2 WqF[144*TSK_Q];
__device__ __align__(256) uint2 WfF[144*TSK_F];

__device__ __forceinline__ void gsync() {
    __syncthreads();
    if (threadIdx.x == 0) {
        __threadfence();
        unsigned g = *(volatile unsigned*)&g_gen;
        unsigned a = atomicAdd(&g_cnt, 1u);
        if (a == gridDim.x - 1u) {
            *(volatile unsigned*)&g_cnt = 0u;
            __threadfence();
            *(volatile unsigned*)&g_gen = g + 1u;
        } else {
            while (*(volatile unsigned*)&g_gen == g) { }
        }
        __threadfence();
    }
    __syncthreads();
}
__device__ __forceinline__ float wsum(float v) {
    #pragma unroll
    for (int o = 16; o > 0; o >>= 1) v += __shfl_xor_sync(0xffffffffu, v, o);
    return v;
}
__device__ __forceinline__ float sigm(float v) { return 1.f / (1.f + expf(-v)); }

// pack two floats to fp16x2 (round-to-nearest)
__device__ __forceinline__ uint32_t pk(float a, float b) {
    __half2 t = __floats2half2_rn(a, b);
    return *(uint32_t*)&t;
}
// split pair into fp16 hi + fp16 residual
__device__ __forceinline__ void split2(float2 v, uint32_t& h, uint32_t& l) {
    float hx = __half2float(__float2half_rn(v.x));
    float hy = __half2float(__float2half_rn(v.y));
    h = pk(hx, hy);
    l = pk(v.x - hx, v.y - hy);
}
__device__ __forceinline__ void mma16816(float* c, const uint32_t* a, const uint32_t* b) {
    asm volatile(
        "mma.sync.aligned.m16n8k16.row.col.f32.f16.f16.f32 "
        "{%0,%1,%2,%3}, {%4,%5,%6,%7}, {%8,%9}, {%0,%1,%2,%3};"
        : "+f"(c[0]), "+f"(c[1]), "+f"(c[2]), "+f"(c[3])
        : "r"(a[0]), "r"(a[1]), "r"(a[2]), "r"(a[3]), "r"(b[0]), "r"(b[1]));
}

__device__ __forceinline__ void stA_slot(uint4* sA, int slotBase, int lane,
                                         const float* p1, const float* p2, int c1) {
    float2 v00 = *(const float2*)(p1 + c1);
    float2 v01 = *(const float2*)(p1 + c1 + 8);
    float2 v10 = *(const float2*)(p2 + c1);
    float2 v11 = *(const float2*)(p2 + c1 + 8);
    uint4 Hv, Lv;
    split2(v00, Hv.x, Lv.x);
    split2(v10, Hv.y, Lv.y);
    split2(v01, Hv.z, Lv.z);
    split2(v11, Hv.w, Lv.w);
    sA[slotBase + lane]      = Hv;
    sA[slotBase + 32 + lane] = Lv;
}
__device__ __forceinline__ void stageA_g(uint4* sA, int buf, const float* Ab, int lda, int c0) {
    const int tid = threadIdx.x;
    if (tid >= 256) return;
    const int kt = tid >> 7, mt = (tid >> 5) & 3, lane = tid & 31;
    const int rr = lane >> 2, kp = lane & 3;
    const float* p1 = Ab + (size_t)(mt * 16 + rr) * lda;
    stA_slot(sA, ((buf * 2 + kt) * 4 + mt) * 64, lane, p1, p1 + 8 * lda, c0 + kt * 16 + kp * 2);
}
__device__ __forceinline__ void stageA_q(uint4* sA, int buf, const float* const* rowp, int c0) {
    const int tid = threadIdx.x;
    if (tid >= 256) return;
    const int mt = tid >> 5, lane = tid & 31;
    const int rr = lane >> 2, kp = lane & 3;
    stA_slot(sA, (buf * 8 + mt) * 64, lane, rowp[mt * 16 + rr], rowp[mt * 16 + rr + 8],
             c0 + kp * 2);
}

// 16 warps, MI=1. 2-pass fp16: (A_hi + A_lo) @ B
template<int KTPS, int MTOT, int NWARP, int NJ, int NGTOT>
__device__ __forceinline__ void comp_stage(const uint4* sA, const uint2* sW,
                                           int buf, int s, float acc[NJ][4]) {
    const int w = threadIdx.x >> 5, lane = threadIdx.x & 31;
    const int mw = w / NWARP, nw = w % NWARP;
    #pragma unroll
    for (int kt = 0; kt < KTPS; kt++) {
        const int ktg = s * KTPS + kt;
        const int sl = ((buf * KTPS + kt) * MTOT + mw) * 64;
        uint4 ah = sA[sl + lane];
        uint4 al = sA[sl + 32 + lane];
        #pragma unroll
        for (int j = 0; j < NJ; j++) {
            uint2 bh = sW[(size_t)(ktg * NGTOT + nw * NJ + j) * 32 + lane];
            mma16816(acc[j], (const uint32_t*)&ah, (const uint32_t*)&bh);
            mma16816(acc[j], (const uint32_t*)&al, (const uint32_t*)&bh);
        }
    }
}
template<int NWARP, int NJ>
__device__ __forceinline__ void epi(const float acc[NJ][4], float* C, int ldc) {
    const int w = threadIdx.x >> 5, lane = threadIdx.x & 31;
    const int mw = w / NWARP, nw = w % NWARP;
    const int g = lane >> 2, tg = lane & 3;
    #pragma unroll
    for (int j = 0; j < NJ; j++) {
        float* d0 = C + (size_t)(mw * 16 + g) * ldc + (nw * NJ + j) * 8 + 2 * tg;
        *(float2*)d0             = make_float2(acc[j][0], acc[j][1]);
        *(float2*)(d0 + 8 * ldc) = make_float2(acc[j][2], acc[j][3]);
    }
}

__global__ void prep_kernel(const float* __restrict__ Wqh, const float* __restrict__ Wah,
                            const float* __restrict__ Wih, const float* __restrict__ Whh,
                            const float* __restrict__ Wq,  const float* __restrict__ Wk,
                            const float* __restrict__ Wv,  const float* __restrict__ Wfuse)
{
    const int idx0 = blockIdx.x * blockDim.x + threadIdx.x;
    const int stride = gridDim.x * blockDim.x;
    const int EG = 144 * 16 * 16 * 32;
    for (int e = idx0; e < EG; e += stride) {
        int lane = e & 31; int r = e >> 5;
        int ng = r & 15; r >>= 4;
        int kt = r & 15; r >>= 4;
        int task = r;
        int nt = task / 6, kc = task % 6;
        int n = nt * 128 + ng * 8 + (lane >> 2);
        int k = kc * 256 + kt * 16 + ((lane & 3) << 1);
        size_t o = (size_t)task * TSK_G + (kt * 16 + ng) * 32 + lane;
        {
            float v0, v1, v2, v3;
            if (k < H_) { v0 = Wqh[(size_t)k*G4H+n]; v1 = Wqh[(size_t)(k+1)*G4H+n];
                          v2 = Wqh[(size_t)(k+8)*G4H+n]; v3 = Wqh[(size_t)(k+9)*G4H+n]; }
            else { int kk = k - H_; v0 = Wah[(size_t)kk*G4H+n]; v1 = Wah[(size_t)(kk+1)*G4H+n];
                   v2 = Wah[(size_t)(kk+8)*G4H+n]; v3 = Wah[(size_t)(kk+9)*G4H+n]; }
            WbaseF[o] = make_uint2(pk(v0, v1), pk(v2, v3));
        }
        {
            float v0, v1, v2, v3;
            if (k < H_) { v0 = Wih[(size_t)k*G4H+n]; v1 = Wih[(size_t)(k+1)*G4H+n];
                          v2 = Wih[(size_t)(k+8)*G4H+n]; v3 = Wih[(size_t)(k+9)*G4H+n]; }
            else { int kk = k - H_; v0 = Whh[(size_t)kk*G4H+n]; v1 = Whh[(size_t)(kk+1)*G4H+n];
                   v2 = Whh[(size_t)(kk+8)*G4H+n]; v3 = Whh[(size_t)(kk+9)*G4H+n]; }
            WgF[o] = make_uint2(pk(v0, v1), pk(v2, v3));
        }
    }
    const int EQ = 144 * 12 * 8 * 32;
    for (int e = idx0; e < EQ; e += stride) {
        int lane = e & 31; int r = e >> 5;
        int ng = r & 7; r >>= 3;
        int kt = r % 12; int task = r / 12;
        int nt = task / 4, kc = task % 4;
        int n = nt * 64 + ng * 8 + (lane >> 2);
        int k = kc * 192 + kt * 16 + ((lane & 3) << 1);
        int ws = n / H_, nc = n - ws * H_;
        const float* W = (ws == 0) ? Wq : ((ws == 1) ? Wk : Wv);
        float v0 = W[(size_t)k*H_+nc],     v1 = W[(size_t)(k+1)*H_+nc];
        float v2 = W[(size_t)(k+8)*H_+nc], v3 = W[(size_t)(k+9)*H_+nc];
        WqF[(size_t)task * TSK_Q + (kt * 8 + ng) * 32 + lane] =
            make_uint2(pk(v0, v1), pk(v2, v3));
    }
    const int EF = 144 * 8 * 8 * 32;
    for (int e = idx0; e < EF; e += stride) {
        int lane = e & 31; int r = e >> 5;
        int ng = r & 7; r >>= 3;
        int kt = r & 7; r >>= 3;
        int task = r;
        int nt = task / 12, kc = task % 12;
        int n = nt * 64 + ng * 8 + (lane >> 2);
        int k = kc * 128 + kt * 16 + ((lane & 3) << 1);
        float v0 = Wfuse[(size_t)k*H_+n],     v1 = Wfuse[(size_t)(k+1)*H_+n];
        float v2 = Wfuse[(size_t)(k+8)*H_+n], v3 = Wfuse[(size_t)(k+9)*H_+n];
        WfF[(size_t)task * TSK_F + (kt * 8 + ng) * 32 + lane] =
            make_uint2(pk(v0, v1), pk(v2, v3));
    }
}

__global__ void __launch_bounds__(NTHREADS, 1)
sqac_kernel(const float* __restrict__ question, const float* __restrict__ answer,
            const float* __restrict__ x, const int* __restrict__ ping,
            const float* __restrict__ h0, const float* __restrict__ c0,
            const float* __restrict__ bqh, const float* __restrict__ bah,
            const float* __restrict__ bih, const float* __restrict__ bhh,
            const float* __restrict__ bq,  const float* __restrict__ bk,
            const float* __restrict__ bv,  const float* __restrict__ bfuse,
            float* __restrict__ out)
{
    extern __shared__ __align__(16) char smem[];
    uint2* sWg = (uint2*)smem;
    uint2* sWq = (uint2*)(smem + SOFF_WQ);
    uint2* sWf = (uint2*)(smem + SOFF_WF);
    uint4* sA  = (uint4*)(smem + SOFF_A);
    const float** rowp = (const float**)(smem + SOFF_RP);

    const int idx0   = blockIdx.x * blockDim.x + threadIdx.x;
    const int stride = gridDim.x * blockDim.x;
    const int bid    = blockIdx.x;
    const int nblk   = gridDim.x;
    const int tid    = threadIdx.x;

    if (bid < 144) {
        const uint4* s1 = (const uint4*)(WbaseF + (size_t)bid * TSK_G);
        for (int i = tid; i < TSK_G / 2; i += NTHREADS) ((uint4*)sWg)[i] = s1[i];
        const uint4* s2 = (const uint4*)(WqF + (size_t)bid * TSK_Q);
        for (int i = tid; i < TSK_Q / 2; i += NTHREADS) ((uint4*)sWq)[i] = s2[i];
        const uint4* s3 = (const uint4*)(WfF + (size_t)bid * TSK_F);
        for (int i = tid; i < TSK_F / 2; i += NTHREADS) ((uint4*)sWf)[i] = s3[i];
    }
    for (int idx = idx0; idx < B_ * H_; idx += stride) {
        g_h[idx] = h0[idx];
        g_c[idx] = c0[idx];
        g_newvAll[idx] = x[idx];
    }
    __syncthreads();

    if (bid < 144) {
        const int nt = bid / 6, kc = bid % 6;
        const float* Ab = (kc < 3) ? (question + kc * 256) : (answer + (kc - 3) * 256);
        float acc[4][4] = {};
        stageA_g(sA, 0, Ab, H_, 0);
        __syncthreads();
        for (int s = 0; s < 8; s++) {
            if (s < 7) stageA_g(sA, (s + 1) & 1, Ab, H_, (s + 1) * 32);
            comp_stage<2, 4, 4, 4, 16>(sA, sWg, s & 1, s, acc);
            __syncthreads();
        }
        epi<4, 4>(acc, g_gp + (size_t)kc * (B_ * G4H) + nt * 128, G4H);
        __syncthreads();
        const uint4* s1 = (const uint4*)(WgF + (size_t)bid * TSK_G);
        for (int i = tid; i < TSK_G / 2; i += NTHREADS) ((uint4*)sWg)[i] = s1[i];
    }
    gsync();

    for (int idx = idx0; idx < B_ * G4H; idx += stride) {
        int n = idx % G4H;
        float s = bqh[n] + bah[n] + bih[n] + bhh[n];
        #pragma unroll
        for (int kc = 0; kc < SK_G; kc++) s += g_gp[(size_t)kc * (B_ * G4H) + idx];
        g_base[idx] = s;
    }
    gsync();

    // =======================================================================
    for (int t = 0; t < T_; t++) {
        // ---- X: gates(t) + QKV(t+1) ----------------------------------------
        if (bid < 144) {
            {
                const int nt = bid / 6, kc = bid % 6;
                const float* Ab = (kc < 3) ? (g_newvAll + (size_t)t * (B_ * H_) + kc * 256)
                                           : (g_h + (kc - 3) * 256);
                float acc[4][4] = {};
                stageA_g(sA, 0, Ab, H_, 0);
                __syncthreads();
                for (int s = 0; s < 8; s++) {
                    if (s < 7) stageA_g(sA, (s + 1) & 1, Ab, H_, (s + 1) * 32);
                    comp_stage<2, 4, 4, 4, 16>(sA, sWg, s & 1, s, acc);
                    __syncthreads();
                }
                epi<4, 4>(acc, g_gp + (size_t)kc * (B_ * G4H) + nt * 128, G4H);
                __syncthreads();
            }
            if (t + 1 < T_) {
                if (tid < 128) {
                    int m = tid, b = m >> 1, s2 = m & 1;
                    const float* p;
                    if (s2) {
                        p = x + ((size_t)(t + 1) * B_ + b) * H_;
                    } else {
                        int pt = ping[b * T_ + (t + 1)];
                        int i2 = pt - 1;
                        i2 = i2 < 0 ? 0 : (i2 > T_ - 1 ? T_ - 1 : i2);
                        p = ((i2 <= t) ? g_newvAll : x) + ((size_t)i2 * B_ + b) * H_;
                    }
                    rowp[m] = p;
                }
                __syncthreads();
                const int nt = bid / 4, kc = bid % 4;
                const int c0 = kc * 192;
                float acc[4][4] = {};
                stageA_q(sA, 0, rowp, c0);
                __syncthreads();
                for (int s = 0; s < 12; s++) {
                    if (s < 11) stageA_q(sA, (s + 1) & 1, rowp, c0 + (s + 1) * 16);
                    comp_stage<1, 8, 2, 4, 8>(sA, sWq, s & 1, s, acc);
                    __syncthreads();
                }
                epi<2, 4>(acc, g_qkvp + (size_t)kc * (2 * B_ * QKVW) + nt * 64, QKVW);
            }
        }
        gsync();

        // ---- Y: attention(t+1) + LSTM(t) ------------------------------------
        if (t + 1 < T_) {
            int wid = bid * (NTHREADS / 32) + (tid >> 5);
            int lane = tid & 31;
            for (int task = wid; task < B_ * NH_; task += nblk * (NTHREADS / 32)) {
                int b = task / NH_, h = task - b * NH_;
                float q[2][2], kk2[2][2], vv[2][2];
                #pragma unroll
                for (int s = 0; s < 2; s++) {
                    int row = (b * 2 + s) * QKVW;
                    #pragma unroll
                    for (int dd = 0; dd < 2; dd++) {
                        int col = h * HD_ + lane + dd * 32;
                        float qv = bq[col], kv = bk[col], vvv = bv[col];
                        #pragma unroll
                        for (int kc = 0; kc < SK_Q; kc++) {
                            const float* p = g_qkvp + (size_t)kc * (2 * B_ * QKVW) + row;
                            qv  += p[col];
                            kv  += p[H_ + col];
                            vvv += p[2 * H_ + col];
                        }
                        q[s][dd] = qv; kk2[s][dd] = kv; vv[s][dd] = vvv;
                    }
                }
                float s00 = wsum(q[0][0]*kk2[0][0] + q[0][1]*kk2[0][1]) * 0.125f;
                float s01 = wsum(q[0][0]*kk2[1][0] + q[0][1]*kk2[1][1]) * 0.125f;
                float s10 = wsum(q[1][0]*kk2[0][0] + q[1][1]*kk2[0][1]) * 0.125f;
                float s11 = wsum(q[1][0]*kk2[1][0] + q[1][1]*kk2[1][1]) * 0.125f;
                float m0 = fmaxf(s00, s01), m1 = fmaxf(s10, s11);
                float e00 = expf(s00 - m0), e01 = expf(s01 - m0);
                float e10 = expf(s10 - m1), e11 = expf(s11 - m1);
                float r0 = 1.f / (e00 + e01), r1 = 1.f / (e10 + e11);
                float p00 = e00 * r0, p01 = e01 * r0, p10 = e10 * r1, p11 = e11 * r1;
                #pragma unroll
                for (int dd = 0; dd < 2; dd++) {
                    int d = lane + dd * 32;
                    g_ctx[b * (2*H_) + h * HD_ + d]      = p00 * vv[0][dd] + p01 * vv[1][dd];
                    g_ctx[b * (2*H_) + H_ + h * HD_ + d] = p10 * vv[0][dd] + p11 * vv[1][dd];
                }
            }
        }
        for (int idx = idx0; idx < B_ * H_; idx += stride) {
            int b = idx / H_, j = idx - b * H_;
            float gg[4];
            #pragma unroll
            for (int u = 0; u < 4; u++) {
                int col = b * G4H + u * H_ + j;
                float s = g_base[col];
                #pragma unroll
                for (int kc = 0; kc < SK_G; kc++) s += g_gp[(size_t)kc * (B_ * G4H) + col];
                gg[u] = s;
            }
            float iv = sigm(gg[0]);
            float fv = sigm(gg[1]);
            float gv = tanhf(gg[2]);
            float ov = sigm(gg[3]);
            float c = fv * g_c[idx] + iv * gv;
            float h = ov * tanhf(c);
            g_c[idx] = c;
            g_h[idx] = h;
            out[((size_t)t * B_ + b) * H_ + j] = h;
            if (t == T_ - 1) {
                out[((size_t)T_ * B_ + b) * H_ + j]       = h;
                out[((size_t)(T_ + 1) * B_ + b) * H_ + j] = c;
            }
        }
        gsync();

        if (t + 1 < T_) {
            // ---- Z: fuse(t+1) ---------------------------------------------
            if (bid < 144) {
                const int nt = bid / 12, kc = bid % 12;
                const float* Ab = g_ctx + kc * 128;
                float acc[2][4] = {};
                stageA_g(sA, 0, Ab, 2 * H_, 0);
                __syncthreads();
                for (int s = 0; s < 4; s++) {
                    if (s < 3) stageA_g(sA, (s + 1) & 1, Ab, 2 * H_, (s + 1) * 32);
                    comp_stage<2, 4, 4, 2, 8>(sA, sWf, s & 1, s, acc);
                    __syncthreads();
                }
                epi<4, 2>(acc, g_fp + (size_t)kc * (B_ * H_) + nt * 64, H_);
            }
            gsync();

            // ---- W: combine fuse + select -> newv(t+1) ----------------------
            for (int idx = idx0; idx < B_ * H_; idx += stride) {
                int b = idx / H_, j = idx - b * H_;
                float e = bfuse[j];
                #pragma unroll
                for (int kc = 0; kc < SK_F; kc++) e += g_fp[(size_t)kc * (B_ * H_) + idx];
                int pt = ping[b * T_ + (t + 1)];
                float right = x[((size_t)(t + 1) * B_ + b) * H_ + j];
                g_newvAll[(size_t)(t + 1) * (B_ * H_) + idx] = (pt > 0) ? e : right;
            }
            gsync();
        }
    }
}

extern "C" void kernel_launch(void* const* d_in, const int* in_sizes, int n_in,
                              void* d_out, int out_size)
{
    (void)in_sizes; (void)n_in; (void)out_size;
    const float* question = (const float*)d_in[0];
    const float* answer   = (const float*)d_in[1];
    const float* x        = (const float*)d_in[2];
    const int*   ping     = (const int*)  d_in[3];
    const float* h0       = (const float*)d_in[4];
    const float* c0       = (const float*)d_in[5];
    const float* Wqh      = (const float*)d_in[6];
    const float* bqh      = (const float*)d_in[7];
    const float* Wah      = (const float*)d_in[8];
    const float* bah      = (const float*)d_in[9];
    const float* Wih      = (const float*)d_in[10];
    const float* bih      = (const float*)d_in[11];
    const float* Whh      = (const float*)d_in[12];
    const float* bhh      = (const float*)d_in[13];
    const float* Wq       = (const float*)d_in[14];
    const float* bq       = (const float*)d_in[15];
    const float* Wk       = (const float*)d_in[16];
    const float* bk       = (const float*)d_in[17];
    const float* Wv       = (const float*)d_in[18];
    const float* bv       = (const float*)d_in[19];
    const float* Wfuse    = (const float*)d_in[20];
    const float* bfuse    = (const float*)d_in[21];

    int dev = 0;
    cudaGetDevice(&dev);
    int nsm = 148;
    cudaDeviceGetAttribute(&nsm, cudaDevAttrMultiProcessorCount, dev);

    cudaFuncSetAttribute(sqac_kernel, cudaFuncAttributeMaxDynamicSharedMemorySize, SMEM_TOTAL);

    prep_kernel<<<nsm * 8, 256>>>(Wqh, Wah, Wih, Whh, Wq, Wk, Wv, Wfuse);
    sqac_kernel<<<nsm, NTHREADS, SMEM_TOTAL>>>(question, answer, x, ping, h0, c0,
                                               bqh, bah, bih, bhh, bq, bk, bv, bfuse,
                                               (float*)d_out);
}

// round 10
// speedup vs baseline: 1.2147x; 1.1260x over previous
#include <cuda_runtime.h>
#include <cuda_fp16.h>
#include <math.h>
#include <stdint.h>

#define T_  256
#define B_  64
#define H_  768
#define NH_ 12
#define HD_ 64
#define G4H 3072
#define QKVW 2304
#define NTHREADS 512
#define SK_G 6
#define SK_Q 4
#define SK_F 12

#define TSK_G (16*16*32)
#define TSK_Q (12*8*32)
#define TSK_F (8*8*32)
#define SOFF_WQ 65536
#define SOFF_WF 90112
#define SOFF_A  106496
#define SOFF_RP 172032
#define SMEM_TOTAL 173056

__device__ __align__(256) float g_newvAll[T_*B_*H_];
__device__ __align__(256) float g_qkvp[SK_Q*2*B_*QKVW];
__device__ __align__(256) float g_ctx[B_*2*H_];
__device__ __align__(256) float g_fp[SK_F*B_*H_];
__device__ __align__(256) float g_gp[SK_G*B_*G4H];
__device__ __align__(256) float g_base[B_*G4H];
__device__ __align__(256) float g_h[B_*H_];
__device__ __align__(256) float g_c[B_*H_];
__device__ unsigned g_cnt = 0;
__device__ unsigned g_gen = 0;

__device__ __align__(256) uint2 WbaseF[144*TSK_G];
__device__ __align__(256) uint2 WgF[144*TSK_G];
__device__ __align__(256) uint2 WqF[144*TSK_Q];
__device__ __align__(256) uint2 WfF[144*TSK_F];

__device__ __forceinline__ void gsync() {
    __syncthreads();
    if (threadIdx.x == 0) {
        __threadfence();
        unsigned g = *(volatile unsigned*)&g_gen;
        unsigned a = atomicAdd(&g_cnt, 1u);
        if (a == gridDim.x - 1u) {
            *(volatile unsigned*)&g_cnt = 0u;
            __threadfence();
            *(volatile unsigned*)&g_gen = g + 1u;
        } else {
            while (*(volatile unsigned*)&g_gen == g) { }
        }
        __threadfence();
    }
    __syncthreads();
}
__device__ __forceinline__ float wsum(float v) {
    #pragma unroll
    for (int o = 16; o > 0; o >>= 1) v += __shfl_xor_sync(0xffffffffu, v, o);
    return v;
}
__device__ __forceinline__ float sigm(float v) { return 1.f / (1.f + expf(-v)); }

__device__ __forceinline__ uint32_t pk(float a, float b) {
    __half2 t = __floats2half2_rn(a, b);
    return *(uint32_t*)&t;
}
__device__ __forceinline__ void split2(float2 v, uint32_t& h, uint32_t& l) {
    float hx = __half2float(__float2half_rn(v.x));
    float hy = __half2float(__float2half_rn(v.y));
    h = pk(hx, hy);
    l = pk(v.x - hx, v.y - hy);
}
__device__ __forceinline__ void mma16816(float* c, const uint32_t* a, const uint32_t* b) {
    asm volatile(
        "mma.sync.aligned.m16n8k16.row.col.f32.f16.f16.f32 "
        "{%0,%1,%2,%3}, {%4,%5,%6,%7}, {%8,%9}, {%0,%1,%2,%3};"
        : "+f"(c[0]), "+f"(c[1]), "+f"(c[2]), "+f"(c[3])
        : "r"(a[0]), "r"(a[1]), "r"(a[2]), "r"(a[3]), "r"(b[0]), "r"(b[1]));
}

__device__ __forceinline__ void stA_slot(uint4* sA, int slotBase, int lane,
                                         const float* p1, const float* p2, int c1) {
    float2 v00 = *(const float2*)(p1 + c1);
    float2 v01 = *(const float2*)(p1 + c1 + 8);
    float2 v10 = *(const float2*)(p2 + c1);
    float2 v11 = *(const float2*)(p2 + c1 + 8);
    uint4 Hv, Lv;
    split2(v00, Hv.x, Lv.x);
    split2(v10, Hv.y, Lv.y);
    split2(v01, Hv.z, Lv.z);
    split2(v11, Hv.w, Lv.w);
    sA[slotBase + lane]      = Hv;
    sA[slotBase + 32 + lane] = Lv;
}

// generic A stage: KS=KTPS*16 k-cols, MR=MTOT*16 rows. 512 threads, 2 slot passes.
template<int KTPS, int MTOT, bool PTR>
__device__ __forceinline__ void stageA(uint4* sA, int buf, const float* Ab, int lda,
                                       const float* const* rowp, int c0) {
    const int tid = threadIdx.x;
    const int lane = tid & 31, wslot = tid >> 5;
    const int rr = lane >> 2, kp = lane & 3;
    #pragma unroll
    for (int r = 0; r < (KTPS * MTOT) / 16; r++) {
        int slot = wslot + r * 16;
        int kt = slot % KTPS, mt = slot / KTPS;
        const float *p1, *p2;
        if (PTR) { p1 = rowp[mt * 16 + rr]; p2 = rowp[mt * 16 + rr + 8]; }
        else     { p1 = Ab + (size_t)(mt * 16 + rr) * lda; p2 = p1 + 8 * lda; }
        stA_slot(sA, ((buf * KTPS + kt) * MTOT + mt) * 64, lane, p1, p2,
                 c0 + kt * 16 + kp * 2);
    }
}

// 16 warps, MI=1; 2-pass fp16 (A_hi + A_lo) @ B
template<int KTPS, int MTOT, int NWARP, int NJ, int NGTOT>
__device__ __forceinline__ void comp_stage(const uint4* sA, const uint2* sW,
                                           int buf, int sBase, float acc[NJ][4]) {
    const int w = threadIdx.x >> 5, lane = threadIdx.x & 31;
    const int mw = w / NWARP, nw = w % NWARP;
    #pragma unroll
    for (int kt = 0; kt < KTPS; kt++) {
        const int ktg = sBase + kt;
        const int sl = ((buf * KTPS + kt) * MTOT + mw) * 64;
        uint4 ah = sA[sl + lane];
        uint4 al = sA[sl + 32 + lane];
        #pragma unroll
        for (int j = 0; j < NJ; j++) {
            uint2 bh = sW[(size_t)(ktg * NGTOT + nw * NJ + j) * 32 + lane];
            mma16816(acc[j], (const uint32_t*)&ah, (const uint32_t*)&bh);
            mma16816(acc[j], (const uint32_t*)&al, (const uint32_t*)&bh);
        }
    }
}
template<int NWARP, int NJ>
__device__ __forceinline__ void epi(const float acc[NJ][4], float* C, int ldc) {
    const int w = threadIdx.x >> 5, lane = threadIdx.x & 31;
    const int mw = w / NWARP, nw = w % NWARP;
    const int g = lane >> 2, tg = lane & 3;
    #pragma unroll
    for (int j = 0; j < NJ; j++) {
        float* d0 = C + (size_t)(mw * 16 + g) * ldc + (nw * NJ + j) * 8 + 2 * tg;
        *(float2*)d0             = make_float2(acc[j][0], acc[j][1]);
        *(float2*)(d0 + 8 * ldc) = make_float2(acc[j][2], acc[j][3]);
    }
}

__global__ void prep_kernel(const float* __restrict__ Wqh, const float* __restrict__ Wah,
                            const float* __restrict__ Wih, const float* __restrict__ Whh,
                            const float* __restrict__ Wq,  const float* __restrict__ Wk,
                            const float* __restrict__ Wv,  const float* __restrict__ Wfuse)
{
    const int idx0 = blockIdx.x * blockDim.x + threadIdx.x;
    const int stride = gridDim.x * blockDim.x;
    const int EG = 144 * 16 * 16 * 32;
    for (int e = idx0; e < EG; e += stride) {
        int lane = e & 31; int r = e >> 5;
        int ng = r & 15; r >>= 4;
        int kt = r & 15; r >>= 4;
        int task = r;
        int nt = task / 6, kc = task % 6;
        int n = nt * 128 + ng * 8 + (lane >> 2);
        int k = kc * 256 + kt * 16 + ((lane & 3) << 1);
        size_t o = (size_t)task * TSK_G + (kt * 16 + ng) * 32 + lane;
        {
            float v0, v1, v2, v3;
            if (k < H_) { v0 = Wqh[(size_t)k*G4H+n]; v1 = Wqh[(size_t)(k+1)*G4H+n];
                          v2 = Wqh[(size_t)(k+8)*G4H+n]; v3 = Wqh[(size_t)(k+9)*G4H+n]; }
            else { int kk = k - H_; v0 = Wah[(size_t)kk*G4H+n]; v1 = Wah[(size_t)(kk+1)*G4H+n];
                   v2 = Wah[(size_t)(kk+8)*G4H+n]; v3 = Wah[(size_t)(kk+9)*G4H+n]; }
            WbaseF[o] = make_uint2(pk(v0, v1), pk(v2, v3));
        }
        {
            float v0, v1, v2, v3;
            if (k < H_) { v0 = Wih[(size_t)k*G4H+n]; v1 = Wih[(size_t)(k+1)*G4H+n];
                          v2 = Wih[(size_t)(k+8)*G4H+n]; v3 = Wih[(size_t)(k+9)*G4H+n]; }
            else { int kk = k - H_; v0 = Whh[(size_t)kk*G4H+n]; v1 = Whh[(size_t)(kk+1)*G4H+n];
                   v2 = Whh[(size_t)(kk+8)*G4H+n]; v3 = Whh[(size_t)(kk+9)*G4H+n]; }
            WgF[o] = make_uint2(pk(v0, v1), pk(v2, v3));
        }
    }
    const int EQ = 144 * 12 * 8 * 32;
    for (int e = idx0; e < EQ; e += stride) {
        int lane = e & 31; int r = e >> 5;
        int ng = r & 7; r >>= 3;
        int kt = r % 12; int task = r / 12;
        int nt = task / 4, kc = task % 4;
        int n = nt * 64 + ng * 8 + (lane >> 2);
        int k = kc * 192 + kt * 16 + ((lane & 3) << 1);
        int ws = n / H_, nc = n - ws * H_;
        const float* W = (ws == 0) ? Wq : ((ws == 1) ? Wk : Wv);
        float v0 = W[(size_t)k*H_+nc],     v1 = W[(size_t)(k+1)*H_+nc];
        float v2 = W[(size_t)(k+8)*H_+nc], v3 = W[(size_t)(k+9)*H_+nc];
        WqF[(size_t)task * TSK_Q + (kt * 8 + ng) * 32 + lane] =
            make_uint2(pk(v0, v1), pk(v2, v3));
    }
    const int EF = 144 * 8 * 8 * 32;
    for (int e = idx0; e < EF; e += stride) {
        int lane = e & 31; int r = e >> 5;
        int ng = r & 7; r >>= 3;
        int kt = r & 7; r >>= 3;
        int task = r;
        int nt = task / 12, kc = task % 12;
        int n = nt * 64 + ng * 8 + (lane >> 2);
        int k = kc * 128 + kt * 16 + ((lane & 3) << 1);
        float v0 = Wfuse[(size_t)k*H_+n],     v1 = Wfuse[(size_t)(k+1)*H_+n];
        float v2 = Wfuse[(size_t)(k+8)*H_+n], v3 = Wfuse[(size_t)(k+9)*H_+n];
        WfF[(size_t)task * TSK_F + (kt * 8 + ng) * 32 + lane] =
            make_uint2(pk(v0, v1), pk(v2, v3));
    }
}

__global__ void __launch_bounds__(NTHREADS, 1)
sqac_kernel(const float* __restrict__ question, const float* __restrict__ answer,
            const float* __restrict__ x, const int* __restrict__ ping,
            const float* __restrict__ h0, const float* __restrict__ c0,
            const float* __restrict__ bqh, const float* __restrict__ bah,
            const float* __restrict__ bih, const float* __restrict__ bhh,
            const float* __restrict__ bq,  const float* __restrict__ bk,
            const float* __restrict__ bv,  const float* __restrict__ bfuse,
            float* __restrict__ out)
{
    extern __shared__ __align__(16) char smem[];
    uint2* sWg = (uint2*)smem;
    uint2* sWq = (uint2*)(smem + SOFF_WQ);
    uint2* sWf = (uint2*)(smem + SOFF_WF);
    uint4* sA  = (uint4*)(smem + SOFF_A);
    const float** rowp = (const float**)(smem + SOFF_RP);

    const int idx0   = blockIdx.x * blockDim.x + threadIdx.x;
    const int stride = gridDim.x * blockDim.x;
    const int bid    = blockIdx.x;
    const int nblk   = gridDim.x;
    const int tid    = threadIdx.x;

    if (bid < 144) {
        const uint4* s1 = (const uint4*)(WbaseF + (size_t)bid * TSK_G);
        for (int i = tid; i < TSK_G / 2; i += NTHREADS) ((uint4*)sWg)[i] = s1[i];
        const uint4* s2 = (const uint4*)(WqF + (size_t)bid * TSK_Q);
        for (int i = tid; i < TSK_Q / 2; i += NTHREADS) ((uint4*)sWq)[i] = s2[i];
        const uint4* s3 = (const uint4*)(WfF + (size_t)bid * TSK_F);
        for (int i = tid; i < TSK_F / 2; i += NTHREADS) ((uint4*)sWf)[i] = s3[i];
    }
    for (int idx = idx0; idx < B_ * H_; idx += stride) {
        g_h[idx] = h0[idx];
        g_c[idx] = c0[idx];
        g_newvAll[idx] = x[idx];
    }
    __syncthreads();

    if (bid < 144) {
        const int nt = bid / 6, kc = bid % 6;
        const float* Ab = (kc < 3) ? (question + kc * 256) : (answer + (kc - 3) * 256);
        float acc[4][4] = {};
        stageA<8, 4, false>(sA, 0, Ab, H_, nullptr, 0);
        __syncthreads();
        for (int s = 0; s < 2; s++) {
            if (s < 1) stageA<8, 4, false>(sA, 1, Ab, H_, nullptr, 128);
            comp_stage<8, 4, 4, 4, 16>(sA, sWg, s & 1, s * 8, acc);
            __syncthreads();
        }
        epi<4, 4>(acc, g_gp + (size_t)kc * (B_ * G4H) + nt * 128, G4H);
        __syncthreads();
        const uint4* s1 = (const uint4*)(WgF + (size_t)bid * TSK_G);
        for (int i = tid; i < TSK_G / 2; i += NTHREADS) ((uint4*)sWg)[i] = s1[i];
    }
    gsync();

    for (int idx = idx0; idx < B_ * G4H; idx += stride) {
        int n = idx % G4H;
        float s = bqh[n] + bah[n] + bih[n] + bhh[n];
        #pragma unroll
        for (int kc = 0; kc < SK_G; kc++) s += g_gp[(size_t)kc * (B_ * G4H) + idx];
        g_base[idx] = s;
    }
    gsync();

    // =======================================================================
    for (int t = 0; t < T_; t++) {
        // ---- X: gates(t) + QKV(t+1) ----------------------------------------
        if (bid < 144) {
            {
                const int nt = bid / 6, kc = bid % 6;
                const float* Ab = (kc < 3) ? (g_newvAll + (size_t)t * (B_ * H_) + kc * 256)
                                           : (g_h + (kc - 3) * 256);
                float acc[4][4] = {};
                stageA<8, 4, false>(sA, 0, Ab, H_, nullptr, 0);
                __syncthreads();
                for (int s = 0; s < 2; s++) {
                    if (s < 1) stageA<8, 4, false>(sA, 1, Ab, H_, nullptr, 128);
                    comp_stage<8, 4, 4, 4, 16>(sA, sWg, s & 1, s * 8, acc);
                    __syncthreads();
                }
                epi<4, 4>(acc, g_gp + (size_t)kc * (B_ * G4H) + nt * 128, G4H);
                __syncthreads();
            }
            if (t + 1 < T_) {
                if (tid < 128) {
                    int m = tid, b = m >> 1, s2 = m & 1;
                    const float* p;
                    if (s2) {
                        p = x + ((size_t)(t + 1) * B_ + b) * H_;
                    } else {
                        int pt = ping[b * T_ + (t + 1)];
                        int i2 = pt - 1;
                        i2 = i2 < 0 ? 0 : (i2 > T_ - 1 ? T_ - 1 : i2);
                        p = ((i2 <= t) ? g_newvAll : x) + ((size_t)i2 * B_ + b) * H_;
                    }
                    rowp[m] = p;
                }
                __syncthreads();
                const int nt = bid / 4, kc = bid % 4;
                const int c0 = kc * 192;
                float acc[4][4] = {};
                stageA<4, 8, true>(sA, 0, nullptr, 0, rowp, c0);
                __syncthreads();
                for (int s = 0; s < 3; s++) {
                    if (s < 2) stageA<4, 8, true>(sA, (s + 1) & 1, nullptr, 0, rowp,
                                                  c0 + (s + 1) * 64);
                    comp_stage<4, 8, 2, 4, 8>(sA, sWq, s & 1, s * 4, acc);
                    __syncthreads();
                }
                epi<2, 4>(acc, g_qkvp + (size_t)kc * (2 * B_ * QKVW) + nt * 64, QKVW);
            }
        }
        gsync();

        // ---- Y: attention(t+1) + LSTM(t) ------------------------------------
        if (t + 1 < T_) {
            int wid = bid * (NTHREADS / 32) + (tid >> 5);
            int lane = tid & 31;
            for (int task = wid; task < B_ * NH_; task += nblk * (NTHREADS / 32)) {
                int b = task / NH_, h = task - b * NH_;
                float q[2][2], kk2[2][2], vv[2][2];
                #pragma unroll
                for (int s = 0; s < 2; s++) {
                    int row = (b * 2 + s) * QKVW;
                    #pragma unroll
                    for (int dd = 0; dd < 2; dd++) {
                        int col = h * HD_ + lane + dd * 32;
                        float qv = bq[col], kv = bk[col], vvv = bv[col];
                        #pragma unroll
                        for (int kc = 0; kc < SK_Q; kc++) {
                            const float* p = g_qkvp + (size_t)kc * (2 * B_ * QKVW) + row;
                            qv  += p[col];
                            kv  += p[H_ + col];
                            vvv += p[2 * H_ + col];
                        }
                        q[s][dd] = qv; kk2[s][dd] = kv; vv[s][dd] = vvv;
                    }
                }
                float s00 = wsum(q[0][0]*kk2[0][0] + q[0][1]*kk2[0][1]) * 0.125f;
                float s01 = wsum(q[0][0]*kk2[1][0] + q[0][1]*kk2[1][1]) * 0.125f;
                float s10 = wsum(q[1][0]*kk2[0][0] + q[1][1]*kk2[0][1]) * 0.125f;
                float s11 = wsum(q[1][0]*kk2[1][0] + q[1][1]*kk2[1][1]) * 0.125f;
                float m0 = fmaxf(s00, s01), m1 = fmaxf(s10, s11);
                float e00 = expf(s00 - m0), e01 = expf(s01 - m0);
                float e10 = expf(s10 - m1), e11 = expf(s11 - m1);
                float r0 = 1.f / (e00 + e01), r1 = 1.f / (e10 + e11);
                float p00 = e00 * r0, p01 = e01 * r0, p10 = e10 * r1, p11 = e11 * r1;
                #pragma unroll
                for (int dd = 0; dd < 2; dd++) {
                    int d = lane + dd * 32;
                    g_ctx[b * (2*H_) + h * HD_ + d]      = p00 * vv[0][dd] + p01 * vv[1][dd];
                    g_ctx[b * (2*H_) + H_ + h * HD_ + d] = p10 * vv[0][dd] + p11 * vv[1][dd];
                }
            }
        }
        for (int idx = idx0; idx < B_ * H_; idx += stride) {
            int b = idx / H_, j = idx - b * H_;
            float gg[4];
            #pragma unroll
            for (int u = 0; u < 4; u++) {
                int col = b * G4H + u * H_ + j;
                float s = g_base[col];
                #pragma unroll
                for (int kc = 0; kc < SK_G; kc++) s += g_gp[(size_t)kc * (B_ * G4H) + col];
                gg[u] = s;
            }
            float iv = sigm(gg[0]);
            float fv = sigm(gg[1]);
            float gv = tanhf(gg[2]);
            float ov = sigm(gg[3]);
            float c = fv * g_c[idx] + iv * gv;
            float h = ov * tanhf(c);
            g_c[idx] = c;
            g_h[idx] = h;
            out[((size_t)t * B_ + b) * H_ + j] = h;
            if (t == T_ - 1) {
                out[((size_t)T_ * B_ + b) * H_ + j]       = h;
                out[((size_t)(T_ + 1) * B_ + b) * H_ + j] = c;
            }
        }
        gsync();

        if (t + 1 < T_) {
            // ---- Z: fuse(t+1), single stage -----------------------------------
            if (bid < 144) {
                const int nt = bid / 12, kc = bid % 12;
                const float* Ab = g_ctx + kc * 128;
                float acc[2][4] = {};
                stageA<8, 4, false>(sA, 0, Ab, 2 * H_, nullptr, 0);
                __syncthreads();
                comp_stage<8, 4, 4, 2, 8>(sA, sWf, 0, 0, acc);
                epi<4, 2>(acc, g_fp + (size_t)kc * (B_ * H_) + nt * 64, H_);
            }
            gsync();

            // ---- W: combine fuse + select -> newv(t+1) --------------------------
            for (int idx = idx0; idx < B_ * H_; idx += stride) {
                int b = idx / H_, j = idx - b * H_;
                float e = bfuse[j];
                #pragma unroll
                for (int kc = 0; kc < SK_F; kc++) e += g_fp[(size_t)kc * (B_ * H_) + idx];
                int pt = ping[b * T_ + (t + 1)];
                float right = x[((size_t)(t + 1) * B_ + b) * H_ + j];
                g_newvAll[(size_t)(t + 1) * (B_ * H_) + idx] = (pt > 0) ? e : right;
            }
            gsync();
        }
    }
}

extern "C" void kernel_launch(void* const* d_in, const int* in_sizes, int n_in,
                              void* d_out, int out_size)
{
    (void)in_sizes; (void)n_in; (void)out_size;
    const float* question = (const float*)d_in[0];
    const float* answer   = (const float*)d_in[1];
    const float* x        = (const float*)d_in[2];
    const int*   ping     = (const int*)  d_in[3];
    const float* h0       = (const float*)d_in[4];
    const float* c0       = (const float*)d_in[5];
    const float* Wqh      = (const float*)d_in[6];
    const float* bqh      = (const float*)d_in[7];
    const float* Wah      = (const float*)d_in[8];
    const float* bah      = (const float*)d_in[9];
    const float* Wih      = (const float*)d_in[10];
    const float* bih      = (const float*)d_in[11];
    const float* Whh      = (const float*)d_in[12];
    const float* bhh      = (const float*)d_in[13];
    const float* Wq       = (const float*)d_in[14];
    const float* bq       = (const float*)d_in[15];
    const float* Wk       = (const float*)d_in[16];
    const float* bk       = (const float*)d_in[17];
    const float* Wv       = (const float*)d_in[18];
    const float* bv       = (const float*)d_in[19];
    const float* Wfuse    = (const float*)d_in[20];
    const float* bfuse    = (const float*)d_in[21];

    int dev = 0;
    cudaGetDevice(&dev);
    int nsm = 148;
    cudaDeviceGetAttribute(&nsm, cudaDevAttrMultiProcessorCount, dev);

    cudaFuncSetAttribute(sqac_kernel, cudaFuncAttributeMaxDynamicSharedMemorySize, SMEM_TOTAL);

    prep_kernel<<<nsm * 8, 256>>>(Wqh, Wah, Wih, Whh, Wq, Wk, Wv, Wfuse);
    sqac_kernel<<<nsm, NTHREADS, SMEM_TOTAL>>>(question, answer, x, ping, h0, c0,
                                               bqh, bah, bih, bhh, bq, bk, bv, bfuse,
                                               (float*)d_out);
}

// round 12
// speedup vs baseline: 1.3217x; 1.0881x over previous
#include <cuda_runtime.h>
#include <cuda_fp16.h>
#include <math.h>
#include <stdint.h>

#define T_  256
#define B_  64
#define H_  768
#define NH_ 12
#define HD_ 64
#define G4H 3072
#define QKVW 2304
#define NTHREADS 512
#define SK_G 6
#define SK_Q 4
#define SK_F 12

#define TSK_G (16*16*32)
#define TSK_Q (12*8*32)
#define TSK_F (8*8*32)
#define SOFF_WQ 65536
#define SOFF_WF 90112
#define SOFF_A  106496
#define SOFF_RP 139264
#define SMEM_TOTAL 140288

__device__ __align__(256) float g_newvAll[T_*B_*H_];
__device__ __align__(256) float g_qkvp[SK_Q*2*B_*QKVW];
__device__ __align__(256) float g_ctx[B_*2*H_];
__device__ __align__(256) float g_fp[SK_F*B_*H_];
__device__ __align__(256) float g_gp[SK_G*B_*G4H];
__device__ __align__(256) float g_base[B_*G4H];
__device__ __align__(256) float g_h[B_*H_];
__device__ __align__(256) float g_c[B_*H_];
__device__ unsigned g_cnt = 0;
__device__ unsigned g_gen = 0;

__device__ __align__(256) uint2 WbaseF[144*TSK_G];
__device__ __align__(256) uint2 WgF[144*TSK_G];
__device__ __align__(256) uint2 WqF[144*TSK_Q];
__device__ __align__(256) uint2 WfF[144*TSK_F];

// replay-safe grid barrier (relative generation + threadfence for L1 visibility)
__device__ __forceinline__ void gsync() {
    __syncthreads();
    if (threadIdx.x == 0) {
        __threadfence();
        unsigned g = *(volatile unsigned*)&g_gen;
        unsigned a = atomicAdd(&g_cnt, 1u);
        if (a == gridDim.x - 1u) {
            *(volatile unsigned*)&g_cnt = 0u;
            __threadfence();
            *(volatile unsigned*)&g_gen = g + 1u;
        } else {
            while (*(volatile unsigned*)&g_gen == g) { }
        }
        __threadfence();
    }
    __syncthreads();
}
__device__ __forceinline__ float wsum(float v) {
    #pragma unroll
    for (int o = 16; o > 0; o >>= 1) v += __shfl_xor_sync(0xffffffffu, v, o);
    return v;
}
__device__ __forceinline__ float sigm(float v) { return 1.f / (1.f + expf(-v)); }

__device__ __forceinline__ uint32_t pk(float a, float b) {
    __half2 t = __floats2half2_rn(a, b);
    return *(uint32_t*)&t;
}
__device__ __forceinline__ void mma16816(float* c, const uint32_t* a, const uint32_t* b) {
    asm volatile(
        "mma.sync.aligned.m16n8k16.row.col.f32.f16.f16.f32 "
        "{%0,%1,%2,%3}, {%4,%5,%6,%7}, {%8,%9}, {%0,%1,%2,%3};"
        : "+f"(c[0]), "+f"(c[1]), "+f"(c[2]), "+f"(c[3])
        : "r"(a[0]), "r"(a[1]), "r"(a[2]), "r"(a[3]), "r"(b[0]), "r"(b[1]));
}

// stage one A fragment (single fp16, 32 uint4 per slot)
__device__ __forceinline__ void stA_slot(uint4* sA, int slotBase, int lane,
                                         const float* p1, const float* p2, int c1) {
    float2 v00 = *(const float2*)(p1 + c1);
    float2 v01 = *(const float2*)(p1 + c1 + 8);
    float2 v10 = *(const float2*)(p2 + c1);
    float2 v11 = *(const float2*)(p2 + c1 + 8);
    uint4 Hv;
    Hv.x = pk(v00.x, v00.y);
    Hv.y = pk(v10.x, v10.y);
    Hv.z = pk(v01.x, v01.y);
    Hv.w = pk(v11.x, v11.y);
    sA[slotBase + lane] = Hv;
}

template<int KTPS, int MTOT, bool PTR>
__device__ __forceinline__ void stageA(uint4* sA, int buf, const float* Ab, int lda,
                                       const float* const* rowp, int c0) {
    const int tid = threadIdx.x;
    const int lane = tid & 31, wslot = tid >> 5;
    const int rr = lane >> 2, kp = lane & 3;
    #pragma unroll
    for (int r = 0; r < (KTPS * MTOT) / 16; r++) {
        int slot = wslot + r * 16;
        int kt = slot % KTPS, mt = slot / KTPS;
        const float *p1, *p2;
        if (PTR) { p1 = rowp[mt * 16 + rr]; p2 = rowp[mt * 16 + rr + 8]; }
        else     { p1 = Ab + (size_t)(mt * 16 + rr) * lda; p2 = p1 + 8 * lda; }
        stA_slot(sA, ((buf * KTPS + kt) * MTOT + mt) * 32, lane, p1, p2,
                 c0 + kt * 16 + kp * 2);
    }
}

// 16 warps, MI=1; single-pass fp16
template<int KTPS, int MTOT, int NWARP, int NJ, int NGTOT>
__device__ __forceinline__ void comp_stage(const uint4* sA, const uint2* sW,
                                           int buf, int sBase, float acc[NJ][4]) {
    const int w = threadIdx.x >> 5, lane = threadIdx.x & 31;
    const int mw = w / NWARP, nw = w % NWARP;
    #pragma unroll
    for (int kt = 0; kt < KTPS; kt++) {
        const int ktg = sBase + kt;
        uint4 ah = sA[((buf * KTPS + kt) * MTOT + mw) * 32 + lane];
        #pragma unroll
        for (int j = 0; j < NJ; j++) {
            uint2 bh = sW[(size_t)(ktg * NGTOT + nw * NJ + j) * 32 + lane];
            mma16816(acc[j], (const uint32_t*)&ah, (const uint32_t*)&bh);
        }
    }
}
template<int NWARP, int NJ>
__device__ __forceinline__ void epi(const float acc[NJ][4], float* C, int ldc) {
    const int w = threadIdx.x >> 5, lane = threadIdx.x & 31;
    const int mw = w / NWARP, nw = w % NWARP;
    const int g = lane >> 2, tg = lane & 3;
    #pragma unroll
    for (int j = 0; j < NJ; j++) {
        float* d0 = C + (size_t)(mw * 16 + g) * ldc + (nw * NJ + j) * 8 + 2 * tg;
        *(float2*)d0             = make_float2(acc[j][0], acc[j][1]);
        *(float2*)(d0 + 8 * ldc) = make_float2(acc[j][2], acc[j][3]);
    }
}

__global__ void prep_kernel(const float* __restrict__ Wqh, const float* __restrict__ Wah,
                            const float* __restrict__ Wih, const float* __restrict__ Whh,
                            const float* __restrict__ Wq,  const float* __restrict__ Wk,
                            const float* __restrict__ Wv,  const float* __restrict__ Wfuse)
{
    const int idx0 = blockIdx.x * blockDim.x + threadIdx.x;
    const int stride = gridDim.x * blockDim.x;
    const int EG = 144 * 16 * 16 * 32;
    for (int e = idx0; e < EG; e += stride) {
        int lane = e & 31; int r = e >> 5;
        int ng = r & 15; r >>= 4;
        int kt = r & 15; r >>= 4;
        int task = r;
        int nt = task / 6, kc = task % 6;
        int n = nt * 128 + ng * 8 + (lane >> 2);
        int k = kc * 256 + kt * 16 + ((lane & 3) << 1);
        size_t o = (size_t)task * TSK_G + (kt * 16 + ng) * 32 + lane;
        {
            float v0, v1, v2, v3;
            if (k < H_) { v0 = Wqh[(size_t)k*G4H+n]; v1 = Wqh[(size_t)(k+1)*G4H+n];
                          v2 = Wqh[(size_t)(k+8)*G4H+n]; v3 = Wqh[(size_t)(k+9)*G4H+n]; }
            else { int kk = k - H_; v0 = Wah[(size_t)kk*G4H+n]; v1 = Wah[(size_t)(kk+1)*G4H+n];
                   v2 = Wah[(size_t)(kk+8)*G4H+n]; v3 = Wah[(size_t)(kk+9)*G4H+n]; }
            WbaseF[o] = make_uint2(pk(v0, v1), pk(v2, v3));
        }
        {
            float v0, v1, v2, v3;
            if (k < H_) { v0 = Wih[(size_t)k*G4H+n]; v1 = Wih[(size_t)(k+1)*G4H+n];
                          v2 = Wih[(size_t)(k+8)*G4H+n]; v3 = Wih[(size_t)(k+9)*G4H+n]; }
            else { int kk = k - H_; v0 = Whh[(size_t)kk*G4H+n]; v1 = Whh[(size_t)(kk+1)*G4H+n];
                   v2 = Whh[(size_t)(kk+8)*G4H+n]; v3 = Whh[(size_t)(kk+9)*G4H+n]; }
            WgF[o] = make_uint2(pk(v0, v1), pk(v2, v3));
        }
    }
    const int EQ = 144 * 12 * 8 * 32;
    for (int e = idx0; e < EQ; e += stride) {
        int lane = e & 31; int r = e >> 5;
        int ng = r & 7; r >>= 3;
        int kt = r % 12; int task = r / 12;
        int nt = task / 4, kc = task % 4;
        int n = nt * 64 + ng * 8 + (lane >> 2);
        int k = kc * 192 + kt * 16 + ((lane & 3) << 1);
        int ws = n / H_, nc = n - ws * H_;
        const float* W = (ws == 0) ? Wq : ((ws == 1) ? Wk : Wv);
        float v0 = W[(size_t)k*H_+nc],     v1 = W[(size_t)(k+1)*H_+nc];
        float v2 = W[(size_t)(k+8)*H_+nc], v3 = W[(size_t)(k+9)*H_+nc];
        WqF[(size_t)task * TSK_Q + (kt * 8 + ng) * 32 + lane] =
            make_uint2(pk(v0, v1), pk(v2, v3));
    }
    const int EF = 144 * 8 * 8 * 32;
    for (int e = idx0; e < EF; e += stride) {
        int lane = e & 31; int r = e >> 5;
        int ng = r & 7; r >>= 3;
        int kt = r & 7; r >>= 3;
        int task = r;
        int nt = task / 12, kc = task % 12;
        int n = nt * 64 + ng * 8 + (lane >> 2);
        int k = kc * 128 + kt * 16 + ((lane & 3) << 1);
        float v0 = Wfuse[(size_t)k*H_+n],     v1 = Wfuse[(size_t)(k+1)*H_+n];
        float v2 = Wfuse[(size_t)(k+8)*H_+n], v3 = Wfuse[(size_t)(k+9)*H_+n];
        WfF[(size_t)task * TSK_F + (kt * 8 + ng) * 32 + lane] =
            make_uint2(pk(v0, v1), pk(v2, v3));
    }
}

__global__ void __launch_bounds__(NTHREADS, 1)
sqac_kernel(const float* __restrict__ question, const float* __restrict__ answer,
            const float* __restrict__ x, const int* __restrict__ ping,
            const float* __restrict__ h0, const float* __restrict__ c0,
            const float* __restrict__ bqh, const float* __restrict__ bah,
            const float* __restrict__ bih, const float* __restrict__ bhh,
            const float* __restrict__ bq,  const float* __restrict__ bk,
            const float* __restrict__ bv,  const float* __restrict__ bfuse,
            float* __restrict__ out)
{
    extern __shared__ __align__(16) char smem[];
    uint2* sWg = (uint2*)smem;
    uint2* sWq = (uint2*)(smem + SOFF_WQ);
    uint2* sWf = (uint2*)(smem + SOFF_WF);
    uint4* sA  = (uint4*)(smem + SOFF_A);
    const float** rowp = (const float**)(smem + SOFF_RP);

    const int idx0   = blockIdx.x * blockDim.x + threadIdx.x;
    const int stride = gridDim.x * blockDim.x;
    const int bid    = blockIdx.x;
    const int nblk   = gridDim.x;
    const int tid    = threadIdx.x;

    if (bid < 144) {
        const uint4* s1 = (const uint4*)(WbaseF + (size_t)bid * TSK_G);
        for (int i = tid; i < TSK_G / 2; i += NTHREADS) ((uint4*)sWg)[i] = s1[i];
        const uint4* s2 = (const uint4*)(WqF + (size_t)bid * TSK_Q);
        for (int i = tid; i < TSK_Q / 2; i += NTHREADS) ((uint4*)sWq)[i] = s2[i];
        const uint4* s3 = (const uint4*)(WfF + (size_t)bid * TSK_F);
        for (int i = tid; i < TSK_F / 2; i += NTHREADS) ((uint4*)sWf)[i] = s3[i];
    }
    for (int idx = idx0; idx < B_ * H_; idx += stride) {
        g_h[idx] = h0[idx];
        g_c[idx] = c0[idx];
        g_newvAll[idx] = x[idx];
    }
    __syncthreads();

    if (bid < 144) {
        const int nt = bid / 6, kc = bid % 6;
        const float* Ab = (kc < 3) ? (question + kc * 256) : (answer + (kc - 3) * 256);
        float acc[4][4] = {};
        stageA<8, 4, false>(sA, 0, Ab, H_, nullptr, 0);
        __syncthreads();
        for (int s = 0; s < 2; s++) {
            if (s < 1) stageA<8, 4, false>(sA, 1, Ab, H_, nullptr, 128);
            comp_stage<8, 4, 4, 4, 16>(sA, sWg, s & 1, s * 8, acc);
            __syncthreads();
        }
        epi<4, 4>(acc, g_gp + (size_t)kc * (B_ * G4H) + nt * 128, G4H);
        __syncthreads();
        const uint4* s1 = (const uint4*)(WgF + (size_t)bid * TSK_G);
        for (int i = tid; i < TSK_G / 2; i += NTHREADS) ((uint4*)sWg)[i] = s1[i];
    }
    gsync();

    for (int idx = idx0; idx < B_ * G4H; idx += stride) {
        int n = idx % G4H;
        float s = bqh[n] + bah[n] + bih[n] + bhh[n];
        #pragma unroll
        for (int kc = 0; kc < SK_G; kc++) s += g_gp[(size_t)kc * (B_ * G4H) + idx];
        g_base[idx] = s;
    }
    gsync();

    // =======================================================================
    for (int t = 0; t < T_; t++) {
        // ---- X: gates(t) + QKV(t+1) ----------------------------------------
        if (bid < 144) {
            {
                const int nt = bid / 6, kc = bid % 6;
                const float* Ab = (kc < 3) ? (g_newvAll + (size_t)t * (B_ * H_) + kc * 256)
                                           : (g_h + (kc - 3) * 256);
                float acc[4][4] = {};
                stageA<8, 4, false>(sA, 0, Ab, H_, nullptr, 0);
                __syncthreads();
                for (int s = 0; s < 2; s++) {
                    if (s < 1) stageA<8, 4, false>(sA, 1, Ab, H_, nullptr, 128);
                    comp_stage<8, 4, 4, 4, 16>(sA, sWg, s & 1, s * 8, acc);
                    __syncthreads();
                }
                epi<4, 4>(acc, g_gp + (size_t)kc * (B_ * G4H) + nt * 128, G4H);
                __syncthreads();
            }
            if (t + 1 < T_) {
                if (tid < 128) {
                    int m = tid, b = m >> 1, s2 = m & 1;
                    const float* p;
                    if (s2) {
                        p = x + ((size_t)(t + 1) * B_ + b) * H_;
                    } else {
                        int pt = ping[b * T_ + (t + 1)];
                        int i2 = pt - 1;
                        i2 = i2 < 0 ? 0 : (i2 > T_ - 1 ? T_ - 1 : i2);
                        p = ((i2 <= t) ? g_newvAll : x) + ((size_t)i2 * B_ + b) * H_;
                    }
                    rowp[m] = p;
                }
                __syncthreads();
                const int nt = bid / 4, kc = bid % 4;
                const int c0 = kc * 192;
                float acc[4][4] = {};
                stageA<4, 8, true>(sA, 0, nullptr, 0, rowp, c0);
                __syncthreads();
                for (int s = 0; s < 3; s++) {
                    if (s < 2) stageA<4, 8, true>(sA, (s + 1) & 1, nullptr, 0, rowp,
                                                  c0 + (s + 1) * 64);
                    comp_stage<4, 8, 2, 4, 8>(sA, sWq, s & 1, s * 4, acc);
                    __syncthreads();
                }
                epi<2, 4>(acc, g_qkvp + (size_t)kc * (2 * B_ * QKVW) + nt * 64, QKVW);
            }
        }
        gsync();

        // ---- Y: attention(t+1) + LSTM(t) ------------------------------------
        if (t + 1 < T_) {
            int wid = bid * (NTHREADS / 32) + (tid >> 5);
            int lane = tid & 31;
            for (int task = wid; task < B_ * NH_; task += nblk * (NTHREADS / 32)) {
                int b = task / NH_, h = task - b * NH_;
                float q[2][2], kk2[2][2], vv[2][2];
                #pragma unroll
                for (int s = 0; s < 2; s++) {
                    int row = (b * 2 + s) * QKVW;
                    #pragma unroll
                    for (int dd = 0; dd < 2; dd++) {
                        int col = h * HD_ + lane + dd * 32;
                        float qv = bq[col], kv = bk[col], vvv = bv[col];
                        #pragma unroll
                        for (int kc = 0; kc < SK_Q; kc++) {
                            const float* p = g_qkvp + (size_t)kc * (2 * B_ * QKVW) + row;
                            qv  += p[col];
                            kv  += p[H_ + col];
                            vvv += p[2 * H_ + col];
                        }
                        q[s][dd] = qv; kk2[s][dd] = kv; vv[s][dd] = vvv;
                    }
                }
                float s00 = wsum(q[0][0]*kk2[0][0] + q[0][1]*kk2[0][1]) * 0.125f;
                float s01 = wsum(q[0][0]*kk2[1][0] + q[0][1]*kk2[1][1]) * 0.125f;
                float s10 = wsum(q[1][0]*kk2[0][0] + q[1][1]*kk2[0][1]) * 0.125f;
                float s11 = wsum(q[1][0]*kk2[1][0] + q[1][1]*kk2[1][1]) * 0.125f;
                float m0 = fmaxf(s00, s01), m1 = fmaxf(s10, s11);
                float e00 = expf(s00 - m0), e01 = expf(s01 - m0);
                float e10 = expf(s10 - m1), e11 = expf(s11 - m1);
                float r0 = 1.f / (e00 + e01), r1 = 1.f / (e10 + e11);
                float p00 = e00 * r0, p01 = e01 * r0, p10 = e10 * r1, p11 = e11 * r1;
                #pragma unroll
                for (int dd = 0; dd < 2; dd++) {
                    int d = lane + dd * 32;
                    g_ctx[b * (2*H_) + h * HD_ + d]      = p00 * vv[0][dd] + p01 * vv[1][dd];
                    g_ctx[b * (2*H_) + H_ + h * HD_ + d] = p10 * vv[0][dd] + p11 * vv[1][dd];
                }
            }
        }
        for (int idx = idx0; idx < B_ * H_; idx += stride) {
            int b = idx / H_, j = idx - b * H_;
            float gg[4];
            #pragma unroll
            for (int u = 0; u < 4; u++) {
                int col = b * G4H + u * H_ + j;
                float s = g_base[col];
                #pragma unroll
                for (int kc = 0; kc < SK_G; kc++) s += g_gp[(size_t)kc * (B_ * G4H) + col];
                gg[u] = s;
            }
            float iv = sigm(gg[0]);
            float fv = sigm(gg[1]);
            float gv = tanhf(gg[2]);
            float ov = sigm(gg[3]);
            float c = fv * g_c[idx] + iv * gv;
            float h = ov * tanhf(c);
            g_c[idx] = c;
            g_h[idx] = h;
            out[((size_t)t * B_ + b) * H_ + j] = h;
            if (t == T_ - 1) {
                out[((size_t)T_ * B_ + b) * H_ + j]       = h;
                out[((size_t)(T_ + 1) * B_ + b) * H_ + j] = c;
            }
        }
        gsync();

        if (t + 1 < T_) {
            // ---- Z: fuse(t+1), single stage -----------------------------------
            if (bid < 144) {
                const int nt = bid / 12, kc = bid % 12;
                const float* Ab = g_ctx + kc * 128;
                float acc[2][4] = {};
                stageA<8, 4, false>(sA, 0, Ab, 2 * H_, nullptr, 0);
                __syncthreads();
                comp_stage<8, 4, 4, 2, 8>(sA, sWf, 0, 0, acc);
                epi<4, 2>(acc, g_fp + (size_t)kc * (B_ * H_) + nt * 64, H_);
            }
            gsync();

            // ---- W: combine fuse + select -> newv(t+1) --------------------------
            for (int idx = idx0; idx < B_ * H_; idx += stride) {
                int b = idx / H_, j = idx - b * H_;
                float e = bfuse[j];
                #pragma unroll
                for (int kc = 0; kc < SK_F; kc++) e += g_fp[(size_t)kc * (B_ * H_) + idx];
                int pt = ping[b * T_ + (t + 1)];
                float right = x[((size_t)(t + 1) * B_ + b) * H_ + j];
                g_newvAll[(size_t)(t + 1) * (B_ * H_) + idx] = (pt > 0) ? e : right;
            }
            gsync();
        }
    }
}

extern "C" void kernel_launch(void* const* d_in, const int* in_sizes, int n_in,
                              void* d_out, int out_size)
{
    (void)in_sizes; (void)n_in; (void)out_size;
    const float* question = (const float*)d_in[0];
    const float* answer   = (const float*)d_in[1];
    const float* x        = (const float*)d_in[2];
    const int*   ping     = (const int*)  d_in[3];
    const float* h0       = (const float*)d_in[4];
    const float* c0       = (const float*)d_in[5];
    const float* Wqh      = (const float*)d_in[6];
    const float* bqh      = (const float*)d_in[7];
    const float* Wah      = (const float*)d_in[8];
    const float* bah      = (const float*)d_in[9];
    const float* Wih      = (const float*)d_in[10];
    const float* bih      = (const float*)d_in[11];
    const float* Whh      = (const float*)d_in[12];
    const float* bhh      = (const float*)d_in[13];
    const float* Wq       = (const float*)d_in[14];
    const float* bq       = (const float*)d_in[15];
    const float* Wk       = (const float*)d_in[16];
    const float* bk       = (const float*)d_in[17];
    const float* Wv       = (const float*)d_in[18];
    const float* bv       = (const float*)d_in[19];
    const float* Wfuse    = (const float*)d_in[20];
    const float* bfuse    = (const float*)d_in[21];

    int dev = 0;
    cudaGetDevice(&dev);
    int nsm = 148;
    cudaDeviceGetAttribute(&nsm, cudaDevAttrMultiProcessorCount, dev);

    cudaFuncSetAttribute(sqac_kernel, cudaFuncAttributeMaxDynamicSharedMemorySize, SMEM_TOTAL);

    prep_kernel<<<nsm * 8, 256>>>(Wqh, Wah, Wih, Whh, Wq, Wk, Wv, Wfuse);
    sqac_kernel<<<nsm, NTHREADS, SMEM_TOTAL>>>(question, answer, x, ping, h0, c0,
                                               bqh, bah, bih, bhh, bq, bk, bv, bfuse,
                                               (float*)d_out);
}